// round 9
// baseline (speedup 1.0000x reference)
#include <cuda_runtime.h>
#include <cuda_bf16.h>

#define BSZ 32
#define TT  200
#define RR  512
#define FF  128
#define BR  4
#define CC  10
#define K2  1024
#define NROWS 2048
#define VTH 0.5f

#define NCTA 128          // all CTAs do GEMM (+2-3 readout tasks each)
#define NTH 1024
#define KT_STRIDE 36
#define ROWSTRIDE 272     // cur section + spk section, each padded to 8
#define OUT0 (BSZ*CC*TT)
#define NTASK (BSZ*CC)    // 320 readout tasks

// -------- device scratch --------
__device__ float    g_currents[TT * RR * BSZ];     // [T][R][B]
__device__ float    g_spk[2][RR * BSZ];            // [R][B] ping-pong
__device__ unsigned short g_pidx16[NROWS * ROWSTRIDE]; // k*36 (fits u16)
__device__ float    g_wv [NROWS * ROWSTRIDE];
__device__ unsigned g_secs[NROWS];                 // ncurP | nspkP<<16
__device__ volatile unsigned g_arrive[NCTA];

__device__ __forceinline__ float sigmoidf_(float x) { return 1.f / (1.f + __expf(-x)); }

__global__ void k_init() {
    int tid = blockIdx.x * blockDim.x + threadIdx.x;
    int n = 2 * RR * BSZ;
    for (int i = tid; i < n; i += gridDim.x * blockDim.x) ((float*)g_spk)[i] = 0.f;
    if (tid < NCTA) g_arrive[tid] = 0;
}

__global__ void k_currents(const float* __restrict__ inp,
                           const float* __restrict__ w_in,
                           const float* __restrict__ b_in) {
    __shared__ float sw[FF];
    int tid = threadIdx.x;
    if (tid < FF) sw[tid] = w_in[tid];
    __syncthreads();
    int lane = tid & 31, wid = tid >> 5;
    long long rid = (long long)blockIdx.x * 8 + wid;
    if (rid >= (long long)BSZ * TT * RR) return;
    const float4* p = (const float4*)inp + rid * (FF / 4);
    float4 v = p[lane];
    float4 w = ((const float4*)sw)[lane];
    float s = v.x * w.x + v.y * w.y + v.z * w.z + v.w * w.w;
    #pragma unroll
    for (int o = 16; o; o >>= 1) s += __shfl_xor_sync(0xffffffffu, s, o);
    if (lane == 0) {
        int r = (int)(rid % RR);
        long long bt = rid / RR;
        int t = (int)(bt % TT);
        int b = (int)(bt / TT);
        g_currents[((long long)t * RR + r) * BSZ + b] = s + b_in[0];
    }
}

__global__ void k_prep(const float* __restrict__ w_rnn,
                       const float* __restrict__ mask) {
    int row = blockIdx.x * 8 + (threadIdx.x >> 5);
    int lane = threadIdx.x & 31;
    if (row >= NROWS) return;
    unsigned short* pp = g_pidx16 + row * ROWSTRIDE;
    float*          wp = g_wv    + row * ROWSTRIDE;

    int base = 0;
    for (int c0 = 0; c0 < 512; c0 += 32) {
        float m = mask[(long long)row * K2 + c0 + lane];
        unsigned bal = __ballot_sync(0xffffffffu, m != 0.f);
        int pre = __popc(bal & ((1u << lane) - 1u));
        if (m != 0.f) {
            pp[base + pre] = (unsigned short)((c0 + lane) * KT_STRIDE);
            wp[base + pre] = w_rnn[(long long)row * K2 + c0 + lane];
        }
        base += __popc(bal);
    }
    int ncur = base, ncurP = (ncur + 7) & ~7;
    if (lane < ncurP - ncur) { pp[ncur + lane] = 0; wp[ncur + lane] = 0.f; }

    base = 0;
    for (int c0 = 512; c0 < K2; c0 += 32) {
        float m = mask[(long long)row * K2 + c0 + lane];
        unsigned bal = __ballot_sync(0xffffffffu, m != 0.f);
        int pre = __popc(bal & ((1u << lane) - 1u));
        if (m != 0.f) {
            pp[ncurP + base + pre] = (unsigned short)((c0 + lane) * KT_STRIDE);
            wp[ncurP + base + pre] = w_rnn[(long long)row * K2 + c0 + lane];
        }
        base += __popc(bal);
    }
    int nspk = base, nspkP = (nspk + 7) & ~7;
    if (lane < nspkP - nspk) { pp[ncurP + nspk + lane] = 0; wp[ncurP + nspk + lane] = 0.f; }
    if (lane == 0) g_secs[row] = (unsigned)ncurP | ((unsigned)nspkP << 16);
}

// smem float offsets
#define SW_OFF   0
#define SI_OFF   (SW_OFF + 16*ROWSTRIDE)              // u16 idx: 16*272 u16 = 2176 f
#define KT_OFF   (SI_OFF + 16*ROWSTRIDE/2)
#define PA_OFF   (KT_OFF + K2*KT_STRIDE)
#define PB_OFF   (PA_OFF + 32*32)
#define SD_OFF   (PB_OFF + 32*32)
#define SM_OFF   (SD_OFF + 16*33)
#define SS_OFF   (SM_OFF + 4*33)
#define HB_OFF   (SS_OFF + 4*33)
#define BT_OFF   (HB_OFF + 128*9)
#define BN_OFF   (BT_OFF + 16)
#define AL_OFF   (BN_OFF + 16)
#define SEC_OFF  (AL_OFF + 8)
#define WRO_OFF  (SEC_OFF + 16)
#define SMEM_FLOATS (WRO_OFF + 3*RR + 8)

__device__ __forceinline__ void gemm_sec16(
    const float* wp, const unsigned short* ip, int cnt,
    const char* ktb, float* dst, int lane)
{
    float a0 = 0.f, a1 = 0.f, a2 = 0.f, a3 = 0.f;
    for (int j = 0; j < cnt; j += 8) {
        float4 wA = *(const float4*)(wp + j);
        float4 wB = *(const float4*)(wp + j + 4);
        uint4  q  = *(const uint4*)(ip + j);      // 8 x u16
        a0 = fmaf(wA.x, *(const float*)(ktb + (q.x & 0xFFFFu) * 4u), a0);
        a1 = fmaf(wA.y, *(const float*)(ktb + (q.x >> 16) * 4u), a1);
        a2 = fmaf(wA.z, *(const float*)(ktb + (q.y & 0xFFFFu) * 4u), a2);
        a3 = fmaf(wA.w, *(const float*)(ktb + (q.y >> 16) * 4u), a3);
        a0 = fmaf(wB.x, *(const float*)(ktb + (q.z & 0xFFFFu) * 4u), a0);
        a1 = fmaf(wB.y, *(const float*)(ktb + (q.z >> 16) * 4u), a1);
        a2 = fmaf(wB.z, *(const float*)(ktb + (q.w & 0xFFFFu) * 4u), a2);
        a3 = fmaf(wB.w, *(const float*)(ktb + (q.w >> 16) * 4u), a3);
    }
    dst[lane] = (a0 + a1) + (a2 + a3);
}

__global__ void __launch_bounds__(NTH, 1)
k_recurrent(const float* __restrict__ gating,
            const float* __restrict__ b_rnn,
            const float* __restrict__ tau_m,
            const float* __restrict__ tau_n,
            const float* __restrict__ w_ro,
            const float* __restrict__ b_ro,
            const float* __restrict__ tau_m_ro,
            float* __restrict__ out) {
    extern __shared__ float smf[];
    int tid = threadIdx.x, lane = tid & 31, wid = tid >> 5;
    int bid = blockIdx.x;

    float*          s_w    = smf + SW_OFF;
    unsigned short* s_idx  = (unsigned short*)(smf + SI_OFF);
    float*          s_kT   = smf + KT_OFF;
    float*          s_pA   = smf + PA_OFF;
    float*          s_pB   = smf + PB_OFF;
    float*          s_d    = smf + SD_OFF;
    float*          s_mem  = smf + SM_OFF;
    float*          s_spk  = smf + SS_OFF;
    float*          s_hist = smf + HB_OFF;
    float*          s_beta = smf + BT_OFF;
    float*          s_brnn = smf + BN_OFF;
    float*          s_alph = smf + AL_OFF;
    unsigned*       s_secs = (unsigned*)(smf + SEC_OFF);
    float*          s_wro  = smf + WRO_OFF;

    int row0 = bid * 16, n0 = bid * 4;
    // readout task range for this CTA (2 or 3 tasks)
    int t0task = (bid * 5) >> 1;
    int t1task = ((bid + 1) * 5) >> 1;
    int ntask = t1task - t0task;

    for (int i = tid; i < 16 * ROWSTRIDE; i += NTH) {
        s_w[i]   = g_wv    [row0 * ROWSTRIDE + i];
        s_idx[i] = g_pidx16[row0 * ROWSTRIDE + i];
    }
    for (int i = tid; i < ntask * RR; i += NTH) {
        int k = i >> 9, r = i & (RR - 1);
        s_wro[i] = w_ro[((t0task + k) % CC) * RR + r];
    }
    if (tid < 16) {
        s_secs[tid] = g_secs[row0 + tid];
        s_beta[tid] = sigmoidf_(tau_n[(n0 + (tid >> 2)) * BR + (tid & 3)]);
        s_brnn[tid] = b_rnn[row0 + tid];
    }
    if (tid < 4) s_alph[tid] = sigmoidf_(tau_m[n0 + tid]);
    for (int i = tid; i < 16 * 33; i += NTH) s_d[i] = 0.f;
    if (tid < 4 * 33) { s_mem[tid] = 0.f; s_spk[tid] = 0.f; }
    __syncthreads();

    const char* ktb = (const char*)s_kT + lane * 4;

    // readout per-warp state (warps 28..27+ntask)
    float ro_m = 0.f, ro_s = 0.f, ro_a = 0.f, ro_b = 0.f;
    int ro_task = 0, ro_bb = 0, ro_tl = 0;
    bool ro_act = (wid >= 28 && wid - 28 < ntask);
    if (ro_act) {
        ro_tl = wid - 28;
        ro_task = t0task + ro_tl;
        ro_bb = ro_task / CC;
        int c_ = ro_task % CC;
        ro_a = sigmoidf_(tau_m_ro[c_]);
        ro_b = b_ro[c_];
    }

    // hoisted fill addressing: thread handles float4 indices tid + j*1024
    int foff_c[4], foff_s[4];
    #pragma unroll
    for (int j = 0; j < 4; j++) {
        int i = tid + j * 1024;
        int r = i >> 3, b4 = i & 7;
        foff_c[j] = r * KT_STRIDE + b4 * 4;
        foff_s[j] = (RR + r) * KT_STRIDE + b4 * 4;
    }

    // prologue: fill currents(0), currents-GEMM(0) -> s_pA
    {
        const float4* cur = (const float4*)g_currents;
        #pragma unroll
        for (int j = 0; j < 4; j++)
            *(float4*)(s_kT + foff_c[j]) = __ldg(cur + tid + j * 1024);
    }
    __syncthreads();
    {
        int row = wid >> 1, half = wid & 1;
        int ncurP = s_secs[row] & 0xFFFF;
        int h0 = (ncurP >> 4) << 3;
        int beg = half ? h0 : 0;
        int cnt = half ? (ncurP - h0) : h0;
        gemm_sec16(s_w + row * ROWSTRIDE + beg, s_idx + row * ROWSTRIDE + beg,
                   cnt, ktb, s_pA + (half * 16 + row) * 32, lane);
    }
    __syncthreads();

    for (int t = 0; t < TT; t++) {
        // (A) poll: all gemm flags >= t (warp 27) + release
        if (wid == 27 && t > 0) {
            bool need = true;
            while (need) {
                bool ok = true;
                #pragma unroll
                for (int k = 0; k < 4; k++)
                    if (g_arrive[lane + k * 32] < (unsigned)t) ok = false;
                need = !__all_sync(0xffffffffu, ok);
                if (need) __nanosleep(20);
            }
        }
        __syncthreads();

        // (B) spike fill: spk(t-1) -> kT spike half (hoisted addresses)
        {
            const float4* sp = (const float4*)(g_spk[t & 1]);
            #pragma unroll
            for (int j = 0; j < 4; j++)
                *(float4*)(s_kT + foff_s[j]) = __ldcg(sp + tid + j * 1024);
        }
        float gpre = 0.f;
        if (wid < 4)
            gpre = __ldg(&gating[((long long)lane * TT + t) * RR + n0 + wid]);
        __syncthreads();

        // (C) spike GEMM -> s_pB
        {
            int row = wid >> 1, half = wid & 1;
            unsigned sec = s_secs[row];
            int ncurP = sec & 0xFFFF, nspkP = sec >> 16;
            int h0 = (nspkP >> 4) << 3;
            int beg = ncurP + (half ? h0 : 0);
            int cnt = half ? (nspkP - h0) : h0;
            gemm_sec16(s_w + row * ROWSTRIDE + beg, s_idx + row * ROWSTRIDE + beg,
                       cnt, ktb, s_pB + (half * 16 + row) * 32, lane);
        }
        __syncthreads();

        // (D) warps0-3: phase3 (neuron=wid, batch=lane) | warps4-31: fill cur(t+1)
        if (wid < 4) {
            int nl = wid, b = lane;
            float g = gpre;
            float lin = 0.f;
            #pragma unroll
            for (int br = 0; br < BR; br++) {
                int row = nl * 4 + br;
                float proj = s_pA[row * 32 + b] + s_pA[(16 + row) * 32 + b]
                           + s_pB[row * 32 + b] + s_pB[(16 + row) * 32 + b]
                           + s_brnn[row];
                float beta = s_beta[row];
                float dold = s_d[row * 33 + b];
                float dnew = beta * dold + (1.f - beta) * proj;
                lin += dnew;
                s_d[row * 33 + b] = g * dnew + (1.f - g) * dold;
            }
            float alpha = s_alph[nl];
            float mold = s_mem[nl * 33 + b];
            float sold = s_spk[nl * 33 + b];
            float mnew = mold * alpha + (1.f - alpha) * lin - VTH * sold;
            float snew = (mnew - VTH) > 0.f ? 1.f : 0.f;
            float mg = g * mnew + (1.f - g) * mold;
            float sg = g * snew + (1.f - g) * sold;
            s_mem[nl * 33 + b] = mg;
            s_spk[nl * 33 + b] = sg;
            g_spk[(t + 1) & 1][(n0 + nl) * BSZ + b] = sg;
            s_hist[(nl * 32 + b) * 9 + (t & 7)] = sg;
            __threadfence();
            asm volatile("bar.sync 1, 128;" ::: "memory");
            if (tid == 0) g_arrive[bid] = (unsigned)(t + 1);
        } else if (t + 1 < TT) {
            const float4* curN = (const float4*)g_currents + (long long)(t + 1) * 4096;
            for (int i = tid - 128; i < 4096; i += NTH - 128) {
                int r = i >> 3, b4 = i & 7;
                *(float4*)(s_kT + r * KT_STRIDE + b4 * 4) = __ldg(curN + i);
            }
        }
        __syncthreads();

        // history dump every 8 steps (coalesced)
        if ((t & 7) == 7 && tid < 256) {
            int pair = tid >> 1, half = tid & 1;
            int nl = pair >> 5, b = pair & 31;
            const float* h = s_hist + pair * 9 + half * 4;
            float4 v = make_float4(h[0], h[1], h[2], h[3]);
            long long base = OUT0 + ((long long)b * RR + (n0 + nl)) * TT + (t - 7);
            *(float4*)(out + base + half * 4) = v;
        }

        // (E) currents GEMM(t+1) -> s_pA (overlaps skew/barrier)
        if (t + 1 < TT) {
            int row = wid >> 1, half = wid & 1;
            int ncurP = s_secs[row] & 0xFFFF;
            int h0 = (ncurP >> 4) << 3;
            int beg = half ? h0 : 0;
            int cnt = half ? (ncurP - h0) : h0;
            gemm_sec16(s_w + row * ROWSTRIDE + beg, s_idx + row * ROWSTRIDE + beg,
                       cnt, ktb, s_pA + (half * 16 + row) * 32, lane);
        }

        // (R) readout for step t-1 from kT spike half (= spk(t-1))
        if (ro_act && t > 0) {
            float sum = 0.f;
            #pragma unroll
            for (int i = 0; i < RR; i += 32)
                sum += s_kT[(RR + i + lane) * KT_STRIDE + ro_bb]
                     * s_wro[ro_tl * RR + i + lane];
            #pragma unroll
            for (int o = 16; o; o >>= 1) sum += __shfl_xor_sync(0xffffffffu, sum, o);
            ro_m = ro_m * ro_a + (1.f - ro_a) * (sum + ro_b) - VTH * ro_s;
            ro_s = (ro_m - VTH) > 0.f ? 1.f : 0.f;
            if (lane == 0) out[(long long)ro_task * TT + (t - 1)] = ro_m;
        }
        // no trailing sync: (A)'s poll+sync covers the next-iteration hazards
    }

    // epilogue: readout for t=199 (needs spk(199) = g_spk[0])
    if (wid == 27) {
        bool need = true;
        while (need) {
            bool ok = true;
            #pragma unroll
            for (int k = 0; k < 4; k++)
                if (g_arrive[lane + k * 32] < (unsigned)TT) ok = false;
            need = !__all_sync(0xffffffffu, ok);
            if (need) __nanosleep(20);
        }
    }
    __syncthreads();
    {
        const float4* sp = (const float4*)(g_spk[TT & 1]);
        #pragma unroll
        for (int j = 0; j < 4; j++)
            *(float4*)(s_kT + foff_s[j]) = __ldcg(sp + tid + j * 1024);
    }
    __syncthreads();
    if (ro_act) {
        float sum = 0.f;
        #pragma unroll
        for (int i = 0; i < RR; i += 32)
            sum += s_kT[(RR + i + lane) * KT_STRIDE + ro_bb]
                 * s_wro[ro_tl * RR + i + lane];
        #pragma unroll
        for (int o = 16; o; o >>= 1) sum += __shfl_xor_sync(0xffffffffu, sum, o);
        ro_m = ro_m * ro_a + (1.f - ro_a) * (sum + ro_b) - VTH * ro_s;
        if (lane == 0) out[(long long)ro_task * TT + (TT - 1)] = ro_m;
    }
}

extern "C" void kernel_launch(void* const* d_in, const int* in_sizes, int n_in,
                              void* d_out, int out_size) {
    const float* inp      = (const float*)d_in[0];
    const float* gating   = (const float*)d_in[1];
    const float* w_in     = (const float*)d_in[2];
    const float* b_in     = (const float*)d_in[3];
    const float* w_rnn    = (const float*)d_in[4];
    const float* b_rnn    = (const float*)d_in[5];
    const float* tau_m    = (const float*)d_in[6];
    const float* tau_n    = (const float*)d_in[7];
    const float* w_ro     = (const float*)d_in[8];
    const float* b_ro     = (const float*)d_in[9];
    const float* tau_m_ro = (const float*)d_in[10];
    const float* mask     = (const float*)d_in[11];
    float* out = (float*)d_out;

    int smem_bytes = SMEM_FLOATS * 4 + 256;   // ~192 KB
    cudaFuncSetAttribute(k_recurrent,
                         cudaFuncAttributeMaxDynamicSharedMemorySize,
                         smem_bytes);

    k_init<<<64, 256>>>();

    long long total_rows = (long long)BSZ * TT * RR;
    int gridA = (int)((total_rows + 7) / 8);
    k_currents<<<gridA, 256>>>(inp, w_in, b_in);

    k_prep<<<NROWS / 8, 256>>>(w_rnn, mask);

    k_recurrent<<<NCTA, NTH, smem_bytes>>>(gating, b_rnn, tau_m, tau_n,
                                           w_ro, b_ro, tau_m_ro, out);
}